// round 7
// baseline (speedup 1.0000x reference)
#include <cuda_runtime.h>

#define TT   512
#define HH   50
#define NTHR 224

typedef unsigned long long u64;

__device__ __forceinline__ u64 pack2(float x) {
    u64 r; asm("mov.b64 %0, {%1,%1};" : "=l"(r) : "f"(x)); return r;
}
__device__ __forceinline__ u64 fma2(u64 a, u64 b, u64 c) {
    u64 d; asm("fma.rn.f32x2 %0, %1, %2, %3;" : "=l"(d) : "l"(a), "l"(b), "l"(c)); return d;
}
__device__ __forceinline__ u64 add2(u64 a, u64 b) {
    u64 d; asm("add.rn.f32x2 %0, %1, %2;" : "=l"(d) : "l"(a), "l"(b)); return d;
}
__device__ __forceinline__ void unpk(u64 v, float& lo, float& hi) {
    asm("mov.b64 {%0, %1}, %2;" : "=f"(lo), "=f"(hi) : "l"(v));
}
__device__ __forceinline__ u64 bfly64(u64 v, int d, unsigned m) {
    unsigned lo, hi;
    asm("mov.b64 {%0, %1}, %2;" : "=r"(lo), "=r"(hi) : "l"(v));
    lo = __shfl_xor_sync(m, lo, d);
    hi = __shfl_xor_sync(m, hi, d);
    u64 r; asm("mov.b64 %0, {%1, %2};" : "=l"(r) : "r"(lo), "r"(hi));
    return r;
}
__device__ __forceinline__ float tanhap(float x) {
    float y; asm("tanh.approx.f32 %0, %1;" : "=f"(y) : "f"(x)); return y;
}
__device__ __forceinline__ float sigap(float x) {
    return fmaf(tanhap(0.5f * x), 0.5f, 0.5f);
}

// Quad decomposition: lanes 4q..4q+3 own unit j = wid*8+q.
//   bit1 (rc): 0 -> rows (i_j, g_j), 1 -> rows (f_j, o_j)
//   bit0 (kh): k-half [0,25) vs [25,50)
// Each lane: 2 rows x 25 k x NP batch-pairs. k-reduce via bfly(1),
// gate exchange via bfly(2), 2 cells per lane (1 for NP3 hi-half).
// h stored [25][16]: unit u at [u%25][(u/25)*8 + b] so both k-halves'
// loads land in one 128B line (1 wavefront per LDS.128).
template<int NP>
__device__ __forceinline__ void run_lstm(
    float (*x_sh)[8], float (*h_sh)[25][16], int b0, int tid,
    const float* __restrict__ x,    const float* __restrict__ W_ih,
    const float* __restrict__ W_hh, const float* __restrict__ b_ih,
    const float* __restrict__ b_hh, const float* __restrict__ fc_w,
    const float* __restrict__ fc_b, float* __restrict__ out)
{
    constexpr int NB = 2 * NP;

    // ---- stage x: global [b][t] -> shared [t][b] ----
    const float4* xg = reinterpret_cast<const float4*>(x);
    for (int idx = tid; idx < NB * 128; idx += NTHR) {
        int bb = idx >> 7, t4 = idx & 127;
        float4 v = xg[(size_t)(b0 + bb) * 128 + t4];
        int t = t4 * 4;
        x_sh[t + 0][bb] = v.x; x_sh[t + 1][bb] = v.y;
        x_sh[t + 2][bb] = v.z; x_sh[t + 3][bb] = v.w;
    }
    for (int i = tid; i < 2 * 25 * 16; i += NTHR) (&h_sh[0][0][0])[i] = 0.f;

    const int lane = tid & 31;
    const int wid  = tid >> 5;
    const int q    = lane >> 2;
    const int sub  = lane & 3;
    const int kh   = sub & 1;
    const int rc   = sub >> 1;
    const int j    = wid * 8 + q;
    const bool act = (j < HH);
    const int jrow = j % 25;
    const int jcol = (j / 25) * 8;

    float w0[25], w1[25];
    u64 wx0 = 0, wx1 = 0, bi0 = 0, bi1 = 0;
    if (act) {
        const int r0 = j + rc * HH;          // i or f row
        const int r1 = j + 2 * HH + rc * HH; // g or o row
        #pragma unroll
        for (int kk = 0; kk < 25; kk++) {
            w0[kk] = W_hh[r0 * HH + kh * 25 + kk];
            w1[kk] = W_hh[r1 * HH + kh * 25 + kk];
        }
        if (kh == 0) {
            wx0 = pack2(W_ih[r0]);
            wx1 = pack2(W_ih[r1]);
            bi0 = pack2(b_ih[r0] + b_hh[r0]);
            bi1 = pack2(b_ih[r1] + b_hh[r1]);
        }
    }
    float c0 = 0.f, c1 = 0.f;

    __syncthreads();

    #pragma unroll 1
    for (int t = 0; t < TT; t++) {
        if (act) {
            const int rb = t & 1, wb = (t + 1) & 1;
            u64 A0[NP], A1[NP];
            if (kh == 0) {
                ulonglong2 xq0 = *reinterpret_cast<const ulonglong2*>(&x_sh[t][0]);
                A0[0] = fma2(xq0.x, wx0, bi0); A0[1] = fma2(xq0.y, wx0, bi0);
                A1[0] = fma2(xq0.x, wx1, bi1); A1[1] = fma2(xq0.y, wx1, bi1);
                if (NP == 4) {
                    ulonglong2 xq1 = *reinterpret_cast<const ulonglong2*>(&x_sh[t][4]);
                    A0[2] = fma2(xq1.x, wx0, bi0); A0[3] = fma2(xq1.y, wx0, bi0);
                    A1[2] = fma2(xq1.x, wx1, bi1); A1[3] = fma2(xq1.y, wx1, bi1);
                } else {
                    u64 xq2 = *reinterpret_cast<const u64*>(&x_sh[t][4]);
                    A0[2] = fma2(xq2, wx0, bi0);
                    A1[2] = fma2(xq2, wx1, bi1);
                }
            } else {
                #pragma unroll
                for (int p = 0; p < NP; p++) { A0[p] = 0; A1[p] = 0; }
            }
            const float* hs = &h_sh[rb][0][kh * 8];
            #pragma unroll
            for (int kk = 0; kk < 25; kk++) {
                u64 w0p = pack2(w0[kk]);
                u64 w1p = pack2(w1[kk]);
                ulonglong2 q0 = *reinterpret_cast<const ulonglong2*>(hs + kk * 16);
                A0[0] = fma2(q0.x, w0p, A0[0]); A0[1] = fma2(q0.y, w0p, A0[1]);
                A1[0] = fma2(q0.x, w1p, A1[0]); A1[1] = fma2(q0.y, w1p, A1[1]);
                if (NP == 4) {
                    ulonglong2 q1 = *reinterpret_cast<const ulonglong2*>(hs + kk * 16 + 4);
                    A0[2] = fma2(q1.x, w0p, A0[2]); A0[3] = fma2(q1.y, w0p, A0[3]);
                    A1[2] = fma2(q1.x, w1p, A1[2]); A1[3] = fma2(q1.y, w1p, A1[3]);
                } else {
                    u64 q2 = *reinterpret_cast<const u64*>(hs + kk * 16 + 4);
                    A0[2] = fma2(q2, w0p, A0[2]);
                    A1[2] = fma2(q2, w1p, A1[2]);
                }
            }

            // ===== k-reduce across bfly(1): lo keeps pairs 0,1; hi keeps rest
            unsigned m = __activemask();
            u64 R00, R01, R10, R11;
            if (NP == 4) {
                u64 s0 = bfly64(kh ? A0[0] : A0[2], 1, m);
                u64 s1 = bfly64(kh ? A1[0] : A1[2], 1, m);
                u64 s2 = bfly64(kh ? A0[1] : A0[3], 1, m);
                u64 s3 = bfly64(kh ? A1[1] : A1[3], 1, m);
                R00 = add2(kh ? A0[2] : A0[0], s0);
                R10 = add2(kh ? A1[2] : A1[0], s1);
                R01 = add2(kh ? A0[3] : A0[1], s2);
                R11 = add2(kh ? A1[3] : A1[1], s3);
            } else {
                u64 s0 = bfly64(kh ? A0[0] : A0[2], 1, m);
                u64 s1 = bfly64(kh ? A1[0] : A1[2], 1, m);
                u64 s2 = bfly64(kh ? A0[1] : 0ULL, 1, m);
                u64 s3 = bfly64(kh ? A1[1] : 0ULL, 1, m);
                R00 = add2(kh ? A0[2] : A0[0], s0);
                R10 = add2(kh ? A1[2] : A1[0], s1);
                R01 = add2(kh ? 0ULL : A0[1], s2);   // junk for kh=1 (unused)
                R11 = add2(kh ? 0ULL : A1[1], s3);
            }

            // ===== gate exchange across bfly(2) + cell update =====
            if (NP == 4 || kh == 0) {
                unsigned m2 = __activemask();
                u64 e0 = bfly64(rc ? R00 : R01, 2, m2);
                u64 e1 = bfly64(rc ? R10 : R11, 2, m2);
                u64 GI, GG, GF, GO;
                if (rc == 0) { GI = R00; GG = R10; GF = e0;  GO = e1;  }
                else         { GF = R01; GO = R11; GI = e0;  GG = e1;  }
                float i0, i1, g0, g1, f0, f1, o0, o1;
                unpk(GI, i0, i1); unpk(GG, g0, g1);
                unpk(GF, f0, f1); unpk(GO, o0, o1);
                c0 = sigap(f0) * c0 + sigap(i0) * tanhap(g0);
                c1 = sigap(f1) * c1 + sigap(i1) * tanhap(g1);
                float2 hn = make_float2(sigap(o0) * tanhap(c0),
                                        sigap(o1) * tanhap(c1));
                const int off = (NP == 4) ? (((kh << 1) | rc) * 2) : (rc * 2);
                *reinterpret_cast<float2*>(&h_sh[wb][jrow][jcol + off]) = hn;
            } else {
                // NP==3, kh==1: one complete pair (batches 4,5); rc0->b4, rc1->b5
                unsigned m2 = __activemask();
                u64 e0 = bfly64(R00, 2, m2);
                u64 e1 = bfly64(R10, 2, m2);
                float iv, gv, fv, ov, d0;
                if (rc == 0) { unpk(R00, iv, d0); unpk(R10, gv, d0);
                               unpk(e0,  fv, d0); unpk(e1,  ov, d0); }
                else         { unpk(e0,  d0, iv); unpk(e1,  d0, gv);
                               unpk(R00, d0, fv); unpk(R10, d0, ov); }
                c0 = sigap(fv) * c0 + sigap(iv) * tanhap(gv);
                h_sh[wb][jrow][jcol + 4 + rc] = sigap(ov) * tanhap(c0);
            }
        }
        __syncthreads();
    }

    // ===== final FC on h_T (buffer 0 since TT is even) =====
    if (tid < NB * 3) {
        int bb = tid / 3, o = tid % 3;
        float s = fc_b[o];
        #pragma unroll
        for (int k = 0; k < HH; k++)
            s += h_sh[0][k % 25][(k / 25) * 8 + bb] * fc_w[o * HH + k];
        out[(size_t)(b0 + bb) * 3 + o] = s;
    }
}

__global__ void __launch_bounds__(NTHR, 2)
lstm_fused(const float* __restrict__ x,    const float* __restrict__ W_ih,
           const float* __restrict__ W_hh, const float* __restrict__ b_ih,
           const float* __restrict__ b_hh, const float* __restrict__ fc_w,
           const float* __restrict__ fc_b, float* __restrict__ out)
{
    __shared__ __align__(16) float x_sh[TT][8];       // 16 KB
    __shared__ __align__(16) float h_sh[2][25][16];   // 3.2 KB, k-half interleaved
    const int bid = blockIdx.x;
    // LUT_classic[bid % 148]: bid and bid+148 share an SM. Pair one 8-batch
    // block with one 6-batch block per SM -> even per-SM load (14 batches).
    if (bid < 148) {
        run_lstm<4>(x_sh, h_sh, bid * 8, threadIdx.x,
                    x, W_ih, W_hh, b_ih, b_hh, fc_w, fc_b, out);
    } else {
        run_lstm<3>(x_sh, h_sh, 1184 + (bid - 148) * 6, threadIdx.x,
                    x, W_ih, W_hh, b_ih, b_hh, fc_w, fc_b, out);
    }
}

extern "C" void kernel_launch(void* const* d_in, const int* in_sizes, int n_in,
                              void* d_out, int out_size) {
    const float* x    = (const float*)d_in[0];
    const float* W_ih = (const float*)d_in[1];
    const float* W_hh = (const float*)d_in[2];
    const float* b_ih = (const float*)d_in[3];
    const float* b_hh = (const float*)d_in[4];
    const float* fc_w = (const float*)d_in[5];
    const float* fc_b = (const float*)d_in[6];
    lstm_fused<<<292, NTHR>>>(x, W_ih, W_hh, b_ih, b_hh, fc_w, fc_b, (float*)d_out);
}

// round 8
// speedup vs baseline: 1.0731x; 1.0731x over previous
#include <cuda_runtime.h>

#define TT   512
#define HH   50
#define NTHR 128

typedef unsigned long long u64;

__device__ __forceinline__ u64 pack2(float x) {
    u64 r; asm("mov.b64 %0, {%1,%1};" : "=l"(r) : "f"(x)); return r;
}
__device__ __forceinline__ u64 fma2(u64 a, u64 b, u64 c) {
    u64 d; asm("fma.rn.f32x2 %0, %1, %2, %3;" : "=l"(d) : "l"(a), "l"(b), "l"(c)); return d;
}
__device__ __forceinline__ void unpk(u64 v, float& lo, float& hi) {
    asm("mov.b64 {%0, %1}, %2;" : "=f"(lo), "=f"(hi) : "l"(v));
}
__device__ __forceinline__ u64 bfly64(u64 v, unsigned m) {
    unsigned lo, hi;
    asm("mov.b64 {%0, %1}, %2;" : "=r"(lo), "=r"(hi) : "l"(v));
    lo = __shfl_xor_sync(m, lo, 1);
    hi = __shfl_xor_sync(m, hi, 1);
    u64 r; asm("mov.b64 %0, {%1, %2};" : "=l"(r) : "r"(lo), "r"(hi));
    return r;
}
__device__ __forceinline__ float tanhap(float x) {
    float y; asm("tanh.approx.f32 %0, %1;" : "=f"(y) : "f"(x)); return y;
}
__device__ __forceinline__ float sigap(float x) {
    return fmaf(tanhap(0.5f * x), 0.5f, 0.5f);
}

// R4 structure (best known): thread owns 2 gate rows, batch-packed f32x2
// accumulators, broadcast LDS.128 of h, bfly(1) gate exchange.
// NP = batch pairs per block (NP=3 -> 6 batches, NP=2 -> 4 batches).
template<int NP>
__device__ __forceinline__ void run_lstm(
    float (*x_sh)[8], float (*h_sh)[HH][8], int b0, int tid,
    const float* __restrict__ x,    const float* __restrict__ W_ih,
    const float* __restrict__ W_hh, const float* __restrict__ b_ih,
    const float* __restrict__ b_hh, const float* __restrict__ fc_w,
    const float* __restrict__ fc_b, float* __restrict__ out)
{
    constexpr int NB = 2 * NP;

    // ---- stage x: global [b][t] -> shared [t][b] ----
    const float4* xg = reinterpret_cast<const float4*>(x);
    for (int idx = tid; idx < NB * 128; idx += NTHR) {
        int bb = idx >> 7, t4 = idx & 127;
        float4 v = xg[(size_t)(b0 + bb) * 128 + t4];
        int t = t4 * 4;
        x_sh[t + 0][bb] = v.x; x_sh[t + 1][bb] = v.y;
        x_sh[t + 2][bb] = v.z; x_sh[t + 3][bb] = v.w;
    }
    for (int i = tid; i < 2 * HH * 8; i += NTHR) (&h_sh[0][0][0])[i] = 0.f;

    // ---- row mapping: even tid=2j -> rows (j: i-gate, j+100: g-gate)
    //                   odd  tid=2j+1 -> rows (j+50: f-gate, j+150: o-gate)
    const bool act = (tid < 2 * HH);
    const int  j   = tid >> 1;
    const int  r0  = (tid & 1) ? (j + HH) : j;
    const int  r1  = r0 + 2 * HH;

    float w0[HH], w1[HH];
    u64 wx0 = 0, wx1 = 0, bi0 = 0, bi1 = 0;
    if (act) {
        #pragma unroll
        for (int k = 0; k < HH; k++) {
            w0[k] = W_hh[r0 * HH + k];
            w1[k] = W_hh[r1 * HH + k];
        }
        wx0 = pack2(W_ih[r0]);
        wx1 = pack2(W_ih[r1]);
        bi0 = pack2(b_ih[r0] + b_hh[r0]);
        bi1 = pack2(b_ih[r1] + b_hh[r1]);
    }
    float c0 = 0.f, c1 = 0.f, c2 = 0.f, c3 = 0.f;

    __syncthreads();

    #pragma unroll 1
    for (int t = 0; t < TT; t++) {
        if (act) {
            // ===== gate phase =====
            u64 A0[NP], A1[NP];
            {
                ulonglong2 q = *reinterpret_cast<const ulonglong2*>(&x_sh[t][0]);
                A0[0] = fma2(q.x, wx0, bi0); A0[1] = fma2(q.y, wx0, bi0);
                A1[0] = fma2(q.x, wx1, bi1); A1[1] = fma2(q.y, wx1, bi1);
                if (NP == 4) {
                    ulonglong2 q1 = *reinterpret_cast<const ulonglong2*>(&x_sh[t][4]);
                    A0[2] = fma2(q1.x, wx0, bi0); A0[3] = fma2(q1.y, wx0, bi0);
                    A1[2] = fma2(q1.x, wx1, bi1); A1[3] = fma2(q1.y, wx1, bi1);
                } else if (NP == 3) {
                    u64 q2 = *reinterpret_cast<const u64*>(&x_sh[t][4]);
                    A0[2] = fma2(q2, wx0, bi0);
                    A1[2] = fma2(q2, wx1, bi1);
                }
            }
            const float* hs = &h_sh[t & 1][0][0];
            #pragma unroll
            for (int k = 0; k < HH; k++) {
                u64 w0p = pack2(w0[k]);
                u64 w1p = pack2(w1[k]);
                ulonglong2 q = *reinterpret_cast<const ulonglong2*>(hs + k * 8);
                A0[0] = fma2(q.x, w0p, A0[0]); A0[1] = fma2(q.y, w0p, A0[1]);
                A1[0] = fma2(q.x, w1p, A1[0]); A1[1] = fma2(q.y, w1p, A1[1]);
                if (NP == 4) {
                    ulonglong2 q1 = *reinterpret_cast<const ulonglong2*>(hs + k * 8 + 4);
                    A0[2] = fma2(q1.x, w0p, A0[2]); A0[3] = fma2(q1.y, w0p, A0[3]);
                    A1[2] = fma2(q1.x, w1p, A1[2]); A1[3] = fma2(q1.y, w1p, A1[3]);
                } else if (NP == 3) {
                    u64 q2 = *reinterpret_cast<const u64*>(hs + k * 8 + 4);
                    A0[2] = fma2(q2, w0p, A0[2]);
                    A1[2] = fma2(q2, w1p, A1[2]);
                }
            }

            unsigned m = __activemask();
            bool ev = !(tid & 1);

            if (NP == 2) {
                // even keeps batches 0,1; odd keeps 2,3 — 2 cells each
                u64 s0 = bfly64(ev ? A0[1] : A0[0], m);
                u64 s1 = bfly64(ev ? A1[1] : A1[0], m);
                u64 GI = ev ? A0[0] : s0;
                u64 GG = ev ? A1[0] : s1;
                u64 GF = ev ? s0 : A0[1];
                u64 GO = ev ? s1 : A1[1];
                float i0, i1, g0, g1, f0, f1, o0, o1;
                unpk(GI, i0, i1); unpk(GG, g0, g1);
                unpk(GF, f0, f1); unpk(GO, o0, o1);
                c0 = sigap(f0) * c0 + sigap(i0) * tanhap(g0);
                c1 = sigap(f1) * c1 + sigap(i1) * tanhap(g1);
                float2 hn = make_float2(sigap(o0) * tanhap(c0),
                                        sigap(o1) * tanhap(c1));
                *reinterpret_cast<float2*>(&h_sh[(t + 1) & 1][j][ev ? 0 : 2]) = hn;
            } else {
                // R4 path: even keeps batches 0-3, odd keeps 4..NB-1
                u64 s0 = bfly64(ev ? A0[2]      : A0[0], m);
                u64 s1 = bfly64(ev ? A1[2]      : A1[0], m);
                u64 s2 = bfly64(ev ? A0[NP - 1] : A0[1], m);
                u64 s3 = bfly64(ev ? A1[NP - 1] : A1[1], m);

                u64 I0 = ev ? A0[0] : s0,  I1 = ev ? A0[1] : s2;
                u64 G0 = ev ? A1[0] : s1,  G1 = ev ? A1[1] : s3;
                u64 F0 = ev ? s0 : A0[2],  F1 = ev ? s2 : A0[NP - 1];
                u64 O0 = ev ? s1 : A1[2],  O1 = ev ? s3 : A1[NP - 1];

                float i0,i1,i2,i3, f0,f1,f2,f3, g0,g1,g2,g3, o0,o1,o2,o3;
                unpk(I0, i0, i1); unpk(I1, i2, i3);
                unpk(F0, f0, f1); unpk(F1, f2, f3);
                unpk(G0, g0, g1); unpk(G1, g2, g3);
                unpk(O0, o0, o1); unpk(O1, o2, o3);

                // odd-lane extras are garbage for NP==3 (bounded, never stored)
                c0 = sigap(f0) * c0 + sigap(i0) * tanhap(g0);
                c1 = sigap(f1) * c1 + sigap(i1) * tanhap(g1);
                c2 = sigap(f2) * c2 + sigap(i2) * tanhap(g2);
                c3 = sigap(f3) * c3 + sigap(i3) * tanhap(g3);
                float4 hn;
                hn.x = sigap(o0) * tanhap(c0);
                hn.y = sigap(o1) * tanhap(c1);
                hn.z = sigap(o2) * tanhap(c2);
                hn.w = sigap(o3) * tanhap(c3);
                float* hw = &h_sh[(t + 1) & 1][j][0];
                if (ev) {
                    *reinterpret_cast<float4*>(hw) = hn;
                } else if (NP == 4) {
                    *reinterpret_cast<float4*>(hw + 4) = hn;
                } else {
                    *reinterpret_cast<float2*>(hw + 4) = make_float2(hn.x, hn.y);
                }
            }
        }
        __syncthreads();
    }

    // ===== final FC on h_T (buffer 0 since TT is even) =====
    if (tid < NB * 3) {
        int bb = tid / 3, o = tid % 3;
        float s = fc_b[o];
        #pragma unroll
        for (int k = 0; k < HH; k++) s += h_sh[0][k][bb] * fc_w[o * HH + k];
        out[(size_t)(b0 + bb) * 3 + o] = s;
    }
}

__global__ void __launch_bounds__(NTHR, 3)
lstm_fused(const float* __restrict__ x,    const float* __restrict__ W_ih,
           const float* __restrict__ W_hh, const float* __restrict__ b_ih,
           const float* __restrict__ b_hh, const float* __restrict__ fc_w,
           const float* __restrict__ fc_b, float* __restrict__ out)
{
    __shared__ __align__(16) float x_sh[TT][8];       // 16 KB
    __shared__ __align__(16) float h_sh[2][HH][8];    // 3.2 KB
    const int bid = blockIdx.x;
    // 3 blocks/SM: LUT_classic places bid, bid+148, bid+296 on the same SM.
    // wave1: NB=6 heavy; waves 2+3: NB=4, stride 145/37 (~3.92) gap-free cover
    // of batches 888..2047 (few duplicated batches -> identical writes, benign).
    if (bid < 148) {
        run_lstm<3>(x_sh, h_sh, bid * 6, threadIdx.x,
                    x, W_ih, W_hh, b_ih, b_hh, fc_w, fc_b, out);
    } else {
        int b0 = 888 + ((bid - 148) * 145) / 37;
        run_lstm<2>(x_sh, h_sh, b0, threadIdx.x,
                    x, W_ih, W_hh, b_ih, b_hh, fc_w, fc_b, out);
    }
}

extern "C" void kernel_launch(void* const* d_in, const int* in_sizes, int n_in,
                              void* d_out, int out_size) {
    const float* x    = (const float*)d_in[0];
    const float* W_ih = (const float*)d_in[1];
    const float* W_hh = (const float*)d_in[2];
    const float* b_ih = (const float*)d_in[3];
    const float* b_hh = (const float*)d_in[4];
    const float* fc_w = (const float*)d_in[5];
    const float* fc_b = (const float*)d_in[6];
    lstm_fused<<<444, NTHR>>>(x, W_ih, W_hh, b_ih, b_hh, fc_w, fc_b, (float*)d_out);
}

// round 9
// speedup vs baseline: 1.1911x; 1.1100x over previous
#include <cuda_runtime.h>

#define TT   512
#define HH   50

typedef unsigned long long u64;

__device__ __forceinline__ u64 pack2(float x) {
    u64 r; asm("mov.b64 %0, {%1,%1};" : "=l"(r) : "f"(x)); return r;
}
__device__ __forceinline__ u64 fma2(u64 a, u64 b, u64 c) {
    u64 d; asm("fma.rn.f32x2 %0, %1, %2, %3;" : "=l"(d) : "l"(a), "l"(b), "l"(c)); return d;
}
__device__ __forceinline__ void unpk(u64 v, float& lo, float& hi) {
    asm("mov.b64 {%0, %1}, %2;" : "=f"(lo), "=f"(hi) : "l"(v));
}
__device__ __forceinline__ u64 bfly64(u64 v, unsigned m) {
    unsigned lo, hi;
    asm("mov.b64 {%0, %1}, %2;" : "=r"(lo), "=r"(hi) : "l"(v));
    lo = __shfl_xor_sync(m, lo, 1);
    hi = __shfl_xor_sync(m, hi, 1);
    u64 r; asm("mov.b64 %0, {%1, %2};" : "=l"(r) : "r"(lo), "r"(hi));
    return r;
}
__device__ __forceinline__ float tanhap(float x) {
    float y; asm("tanh.approx.f32 %0, %1;" : "=f"(y) : "f"(x)); return y;
}
__device__ __forceinline__ float sigap(float x) {
    return fmaf(tanhap(0.5f * x), 0.5f, 0.5f);
}

#define NBAR(id) asm volatile("bar.sync %0, 128;" :: "r"(id) : "memory")

// One warp-group (128 threads) = an independent R4-style LSTM over NB=2*NP
// batches, synchronized ONLY by its own named barrier BID. Two groups per
// 256-thread block run mutually staggered so one group's MUFU/barrier tail
// hides under the other group's FFMA2 burst.
template<int NP, int BID>
__device__ __forceinline__ void run_group(
    float (*x_sh)[8], float (*h_sh)[HH][8], float* sink, int b0, int tid,
    bool stagger,
    const float* __restrict__ x,    const float* __restrict__ W_ih,
    const float* __restrict__ W_hh, const float* __restrict__ b_ih,
    const float* __restrict__ b_hh, const float* __restrict__ fc_w,
    const float* __restrict__ fc_b, float* __restrict__ out)
{
    constexpr int NB = 2 * NP;

    // ---- stage x: global [b][t] -> shared [t][b] (group-local threads) ----
    const float4* xg = reinterpret_cast<const float4*>(x);
    for (int idx = tid; idx < NB * 128; idx += 128) {
        int bb = idx >> 7, t4 = idx & 127;
        float4 v = xg[(size_t)(b0 + bb) * 128 + t4];
        int t = t4 * 4;
        x_sh[t + 0][bb] = v.x; x_sh[t + 1][bb] = v.y;
        x_sh[t + 2][bb] = v.z; x_sh[t + 3][bb] = v.w;
    }
    for (int i = tid; i < 2 * HH * 8; i += 128) (&h_sh[0][0][0])[i] = 0.f;

    // ---- row mapping: even tid=2j -> rows (j: i-gate, j+100: g-gate)
    //                   odd  tid=2j+1 -> rows (j+50: f-gate, j+150: o-gate)
    const bool act = (tid < 2 * HH);
    const int  j   = tid >> 1;
    const int  r0  = (tid & 1) ? (j + HH) : j;
    const int  r1  = r0 + 2 * HH;

    float w0[HH], w1[HH];
    u64 wx0 = 0, wx1 = 0, bi0 = 0, bi1 = 0;
    if (act) {
        #pragma unroll
        for (int k = 0; k < HH; k++) {
            w0[k] = W_hh[r0 * HH + k];
            w1[k] = W_hh[r1 * HH + k];
        }
        wx0 = pack2(W_ih[r0]);
        wx1 = pack2(W_ih[r1]);
        bi0 = pack2(b_ih[r0] + b_hh[r0]);
        bi1 = pack2(b_ih[r1] + b_hh[r1]);
    }
    float c0 = 0.f, c1 = 0.f, c2 = 0.f, c3 = 0.f;

    // ---- anti-phase stagger: ~600-cyc dependent-FMA delay for this group ----
    if (stagger) {
        float d = b_hh[0];
        #pragma unroll 1
        for (int i = 0; i < 150; i++) d = fmaf(d, 1.0000001f, 1e-7f);
        if (d == -1e30f) *sink = d;   // never true; defeats DCE only
    }

    NBAR(BID);

    #pragma unroll 1
    for (int t = 0; t < TT; t++) {
        if (act) {
            // ===== gate phase =====
            u64 A0[NP], A1[NP];
            {
                ulonglong2 q = *reinterpret_cast<const ulonglong2*>(&x_sh[t][0]);
                A0[0] = fma2(q.x, wx0, bi0); A0[1] = fma2(q.y, wx0, bi0);
                A1[0] = fma2(q.x, wx1, bi1); A1[1] = fma2(q.y, wx1, bi1);
                if (NP == 4) {
                    ulonglong2 q1 = *reinterpret_cast<const ulonglong2*>(&x_sh[t][4]);
                    A0[2] = fma2(q1.x, wx0, bi0); A0[3] = fma2(q1.y, wx0, bi0);
                    A1[2] = fma2(q1.x, wx1, bi1); A1[3] = fma2(q1.y, wx1, bi1);
                } else {
                    u64 q2 = *reinterpret_cast<const u64*>(&x_sh[t][4]);
                    A0[2] = fma2(q2, wx0, bi0);
                    A1[2] = fma2(q2, wx1, bi1);
                }
            }
            const float* hs = &h_sh[t & 1][0][0];
            #pragma unroll
            for (int k = 0; k < HH; k++) {
                u64 w0p = pack2(w0[k]);
                u64 w1p = pack2(w1[k]);
                ulonglong2 q = *reinterpret_cast<const ulonglong2*>(hs + k * 8);
                A0[0] = fma2(q.x, w0p, A0[0]); A0[1] = fma2(q.y, w0p, A0[1]);
                A1[0] = fma2(q.x, w1p, A1[0]); A1[1] = fma2(q.y, w1p, A1[1]);
                if (NP == 4) {
                    ulonglong2 q1 = *reinterpret_cast<const ulonglong2*>(hs + k * 8 + 4);
                    A0[2] = fma2(q1.x, w0p, A0[2]); A0[3] = fma2(q1.y, w0p, A0[3]);
                    A1[2] = fma2(q1.x, w1p, A1[2]); A1[3] = fma2(q1.y, w1p, A1[3]);
                } else {
                    u64 q2 = *reinterpret_cast<const u64*>(hs + k * 8 + 4);
                    A0[2] = fma2(q2, w0p, A0[2]);
                    A1[2] = fma2(q2, w1p, A1[2]);
                }
            }

            // ===== exchange: even keeps batches 0-3, odd keeps 4..NB-1 =====
            unsigned m = __activemask();
            bool ev = !(tid & 1);
            u64 s0 = bfly64(ev ? A0[2]      : A0[0], m);
            u64 s1 = bfly64(ev ? A1[2]      : A1[0], m);
            u64 s2 = bfly64(ev ? A0[NP - 1] : A0[1], m);
            u64 s3 = bfly64(ev ? A1[NP - 1] : A1[1], m);

            u64 I0 = ev ? A0[0] : s0,  I1 = ev ? A0[1] : s2;
            u64 G0 = ev ? A1[0] : s1,  G1 = ev ? A1[1] : s3;
            u64 F0 = ev ? s0 : A0[2],  F1 = ev ? s2 : A0[NP - 1];
            u64 O0 = ev ? s1 : A1[2],  O1 = ev ? s3 : A1[NP - 1];

            float i0,i1,i2,i3, f0,f1,f2,f3, g0,g1,g2,g3, o0,o1,o2,o3;
            unpk(I0, i0, i1); unpk(I1, i2, i3);
            unpk(F0, f0, f1); unpk(F1, f2, f3);
            unpk(G0, g0, g1); unpk(G1, g2, g3);
            unpk(O0, o0, o1); unpk(O1, o2, o3);

            // odd-lane extras are garbage for NP==3 (bounded, never stored)
            c0 = sigap(f0) * c0 + sigap(i0) * tanhap(g0);
            c1 = sigap(f1) * c1 + sigap(i1) * tanhap(g1);
            c2 = sigap(f2) * c2 + sigap(i2) * tanhap(g2);
            c3 = sigap(f3) * c3 + sigap(i3) * tanhap(g3);
            float4 hn;
            hn.x = sigap(o0) * tanhap(c0);
            hn.y = sigap(o1) * tanhap(c1);
            hn.z = sigap(o2) * tanhap(c2);
            hn.w = sigap(o3) * tanhap(c3);
            float* hw = &h_sh[(t + 1) & 1][j][0];
            if (ev) {
                *reinterpret_cast<float4*>(hw) = hn;
            } else if (NP == 4) {
                *reinterpret_cast<float4*>(hw + 4) = hn;
            } else {
                *reinterpret_cast<float2*>(hw + 4) = make_float2(hn.x, hn.y);
            }
        }
        NBAR(BID);
    }

    // ===== final FC on h_T (buffer 0 since TT is even) =====
    if (tid < NB * 3) {
        int bb = tid / 3, o = tid % 3;
        float s = fc_b[o];
        #pragma unroll
        for (int k = 0; k < HH; k++) s += h_sh[0][k][bb] * fc_w[o * HH + k];
        out[(size_t)(b0 + bb) * 3 + o] = s;
    }
}

__global__ void __launch_bounds__(256, 1)
lstm_fused(const float* __restrict__ x,    const float* __restrict__ W_ih,
           const float* __restrict__ W_hh, const float* __restrict__ b_ih,
           const float* __restrict__ b_hh, const float* __restrict__ fc_w,
           const float* __restrict__ fc_b, float* __restrict__ out)
{
    __shared__ __align__(16) float xA[TT][8];         // 16 KB
    __shared__ __align__(16) float xB[TT][8];         // 16 KB
    __shared__ __align__(16) float hA[2][HH][8];      // 3.2 KB
    __shared__ __align__(16) float hB[2][HH][8];      // 3.2 KB
    __shared__ float sink;

    // 14 batches per block, one block per SM (grid 147 <= 148, wave 1).
    // Cap b0 so the last block recomputes a few batches (identical writes).
    const int b0  = min((int)blockIdx.x * 14, 2048 - 14);
    const int tid = threadIdx.x;

    if (tid < 128) {
        // group A: 8 batches, named barrier 1, no stagger
        run_group<4, 1>(xA, hA, &sink, b0, tid, false,
                        x, W_ih, W_hh, b_ih, b_hh, fc_w, fc_b, out);
    } else {
        // group B: 6 batches, named barrier 2, staggered ~600 cyc
        run_group<3, 2>(xB, hB, &sink, b0 + 8, tid - 128, true,
                        x, W_ih, W_hh, b_ih, b_hh, fc_w, fc_b, out);
    }
}

extern "C" void kernel_launch(void* const* d_in, const int* in_sizes, int n_in,
                              void* d_out, int out_size) {
    const float* x    = (const float*)d_in[0];
    const float* W_ih = (const float*)d_in[1];
    const float* W_hh = (const float*)d_in[2];
    const float* b_ih = (const float*)d_in[3];
    const float* b_hh = (const float*)d_in[4];
    const float* fc_w = (const float*)d_in[5];
    const float* fc_b = (const float*)d_in[6];
    lstm_fused<<<147, 256>>>(x, W_ih, W_hh, b_ih, b_hh, fc_w, fc_b, (float*)d_out);
}

// round 10
// speedup vs baseline: 1.2156x; 1.0205x over previous
#include <cuda_runtime.h>

#define TT   512
#define HH   50

typedef unsigned long long u64;

__device__ __forceinline__ u64 pack2(float x) {
    u64 r; asm("mov.b64 %0, {%1,%1};" : "=l"(r) : "f"(x)); return r;
}
__device__ __forceinline__ u64 fma2(u64 a, u64 b, u64 c) {
    u64 d; asm("fma.rn.f32x2 %0, %1, %2, %3;" : "=l"(d) : "l"(a), "l"(b), "l"(c)); return d;
}
__device__ __forceinline__ void unpk(u64 v, float& lo, float& hi) {
    asm("mov.b64 {%0, %1}, %2;" : "=f"(lo), "=f"(hi) : "l"(v));
}
__device__ __forceinline__ u64 bfly64(u64 v, unsigned m) {
    unsigned lo, hi;
    asm("mov.b64 {%0, %1}, %2;" : "=r"(lo), "=r"(hi) : "l"(v));
    lo = __shfl_xor_sync(m, lo, 1);
    hi = __shfl_xor_sync(m, hi, 1);
    u64 r; asm("mov.b64 %0, {%1, %2};" : "=l"(r) : "r"(lo), "r"(hi));
    return r;
}
__device__ __forceinline__ float tanhap(float x) {
    float y; asm("tanh.approx.f32 %0, %1;" : "=f"(y) : "f"(x)); return y;
}
__device__ __forceinline__ float sigap(float x) {
    return fmaf(tanhap(0.5f * x), 0.5f, 0.5f);
}

#define NBAR(id) asm volatile("bar.sync %0, 128;" :: "r"(id) : "memory")

// One warp-group (128 threads) = independent LSTM over NB=2*NP batches,
// synchronized only by named barrier BID. XW = x_sh row width (floats).
template<int NP, int BID, int XW>
__device__ __forceinline__ void run_group(
    float* x_sh, float (*h_sh)[HH][8], float* sink, int b0, int tid,
    int stagger_iters,
    const float* __restrict__ x,    const float* __restrict__ W_ih,
    const float* __restrict__ W_hh, const float* __restrict__ b_ih,
    const float* __restrict__ b_hh, const float* __restrict__ fc_w,
    const float* __restrict__ fc_b, float* __restrict__ out)
{
    constexpr int NB = 2 * NP;

    // ---- stage x: global [b][t] -> shared [t][b] ----
    const float4* xg = reinterpret_cast<const float4*>(x);
    for (int idx = tid; idx < NB * 128; idx += 128) {
        int bb = idx >> 7, t4 = idx & 127;
        float4 v = xg[(size_t)(b0 + bb) * 128 + t4];
        int t = t4 * 4;
        x_sh[(t + 0) * XW + bb] = v.x; x_sh[(t + 1) * XW + bb] = v.y;
        x_sh[(t + 2) * XW + bb] = v.z; x_sh[(t + 3) * XW + bb] = v.w;
    }
    for (int i = tid; i < 2 * HH * 8; i += 128) (&h_sh[0][0][0])[i] = 0.f;

    // ---- row mapping: even tid=2j -> rows (j: i-gate, j+100: g-gate)
    //                   odd  tid=2j+1 -> rows (j+50: f-gate, j+150: o-gate)
    const bool act = (tid < 2 * HH);
    const int  j   = tid >> 1;
    const int  r0  = (tid & 1) ? (j + HH) : j;
    const int  r1  = r0 + 2 * HH;

    float w0[HH], w1[HH];
    u64 wx0 = 0, wx1 = 0, bi0 = 0, bi1 = 0;
    if (act) {
        #pragma unroll
        for (int k = 0; k < HH; k++) {
            w0[k] = W_hh[r0 * HH + k];
            w1[k] = W_hh[r1 * HH + k];
        }
        wx0 = pack2(W_ih[r0]);
        wx1 = pack2(W_ih[r1]);
        bi0 = pack2(b_ih[r0] + b_hh[r0]);
        bi1 = pack2(b_ih[r1] + b_hh[r1]);
    }
    float c0 = 0.f, c1 = 0.f, c2 = 0.f, c3 = 0.f;

    // ---- anti-phase stagger: dependent-FMA delay ----
    if (stagger_iters) {
        float d = b_hh[0];
        #pragma unroll 1
        for (int i = 0; i < stagger_iters; i++) d = fmaf(d, 1.0000001f, 1e-7f);
        if (d == -1e30f) *sink = d;   // never true; defeats DCE only
    }

    NBAR(BID);

    #pragma unroll 1
    for (int t = 0; t < TT; t++) {
        if (act) {
            // ===== gate phase =====
            u64 A0[NP], A1[NP];
            {
                ulonglong2 q = *reinterpret_cast<const ulonglong2*>(&x_sh[t * XW]);
                A0[0] = fma2(q.x, wx0, bi0); A0[1] = fma2(q.y, wx0, bi0);
                A1[0] = fma2(q.x, wx1, bi1); A1[1] = fma2(q.y, wx1, bi1);
                if (NP == 3) {
                    u64 q2 = *reinterpret_cast<const u64*>(&x_sh[t * XW + 4]);
                    A0[2] = fma2(q2, wx0, bi0);
                    A1[2] = fma2(q2, wx1, bi1);
                }
            }
            const float* hs = &h_sh[t & 1][0][0];
            #pragma unroll
            for (int k = 0; k < HH; k++) {
                u64 w0p = pack2(w0[k]);
                u64 w1p = pack2(w1[k]);
                ulonglong2 q = *reinterpret_cast<const ulonglong2*>(hs + k * 8);
                A0[0] = fma2(q.x, w0p, A0[0]); A0[1] = fma2(q.y, w0p, A0[1]);
                A1[0] = fma2(q.x, w1p, A1[0]); A1[1] = fma2(q.y, w1p, A1[1]);
                if (NP == 3) {
                    u64 q2 = *reinterpret_cast<const u64*>(hs + k * 8 + 4);
                    A0[2] = fma2(q2, w0p, A0[2]);
                    A1[2] = fma2(q2, w1p, A1[2]);
                }
            }

            unsigned m = __activemask();
            bool ev = !(tid & 1);

            if (NP == 2) {
                // even keeps batches 0,1; odd keeps 2,3 — 2 cells each
                u64 s0 = bfly64(ev ? A0[1] : A0[0], m);
                u64 s1 = bfly64(ev ? A1[1] : A1[0], m);
                u64 GI = ev ? A0[0] : s0;
                u64 GG = ev ? A1[0] : s1;
                u64 GF = ev ? s0 : A0[1];
                u64 GO = ev ? s1 : A1[1];
                float i0, i1, g0, g1, f0, f1, o0, o1;
                unpk(GI, i0, i1); unpk(GG, g0, g1);
                unpk(GF, f0, f1); unpk(GO, o0, o1);
                c0 = sigap(f0) * c0 + sigap(i0) * tanhap(g0);
                c1 = sigap(f1) * c1 + sigap(i1) * tanhap(g1);
                float2 hn = make_float2(sigap(o0) * tanhap(c0),
                                        sigap(o1) * tanhap(c1));
                *reinterpret_cast<float2*>(&h_sh[(t + 1) & 1][j][ev ? 0 : 2]) = hn;
            } else {
                // NP==3: even keeps batches 0-3, odd keeps 4,5 (+2 garbage)
                u64 s0 = bfly64(ev ? A0[2] : A0[0], m);
                u64 s1 = bfly64(ev ? A1[2] : A1[0], m);
                u64 s2 = bfly64(ev ? A0[2] : A0[1], m);
                u64 s3 = bfly64(ev ? A1[2] : A1[1], m);

                u64 I0 = ev ? A0[0] : s0,  I1 = ev ? A0[1] : s2;
                u64 G0 = ev ? A1[0] : s1,  G1 = ev ? A1[1] : s3;
                u64 F0 = ev ? s0 : A0[2],  F1 = ev ? s2 : A0[2];
                u64 O0 = ev ? s1 : A1[2],  O1 = ev ? s3 : A1[2];

                float i0,i1,i2,i3, f0,f1,f2,f3, g0,g1,g2,g3, o0,o1,o2,o3;
                unpk(I0, i0, i1); unpk(I1, i2, i3);
                unpk(F0, f0, f1); unpk(F1, f2, f3);
                unpk(G0, g0, g1); unpk(G1, g2, g3);
                unpk(O0, o0, o1); unpk(O1, o2, o3);

                c0 = sigap(f0) * c0 + sigap(i0) * tanhap(g0);
                c1 = sigap(f1) * c1 + sigap(i1) * tanhap(g1);
                c2 = sigap(f2) * c2 + sigap(i2) * tanhap(g2);
                c3 = sigap(f3) * c3 + sigap(i3) * tanhap(g3);
                float4 hn;
                hn.x = sigap(o0) * tanhap(c0);
                hn.y = sigap(o1) * tanhap(c1);
                hn.z = sigap(o2) * tanhap(c2);
                hn.w = sigap(o3) * tanhap(c3);
                float* hw = &h_sh[(t + 1) & 1][j][0];
                if (ev) {
                    *reinterpret_cast<float4*>(hw) = hn;
                } else {
                    *reinterpret_cast<float2*>(hw + 4) = make_float2(hn.x, hn.y);
                }
            }
        }
        NBAR(BID);
    }

    // ===== final FC on h_T (buffer 0 since TT is even) =====
    if (tid < NB * 3) {
        int bb = tid / 3, o = tid % 3;
        float s = fc_b[o];
        #pragma unroll
        for (int k = 0; k < HH; k++) s += h_sh[0][k][bb] * fc_w[o * HH + k];
        out[(size_t)(b0 + bb) * 3 + o] = s;
    }
}

__global__ void __launch_bounds__(384, 1)
lstm_fused(const float* __restrict__ x,    const float* __restrict__ W_ih,
           const float* __restrict__ W_hh, const float* __restrict__ b_ih,
           const float* __restrict__ b_hh, const float* __restrict__ fc_w,
           const float* __restrict__ fc_b, float* __restrict__ out)
{
    __shared__ __align__(16) float xA[TT * 8];        // 16 KB (6 used, pad 8)
    __shared__ __align__(16) float xB[TT * 4];        // 8 KB
    __shared__ __align__(16) float xC[TT * 4];        // 8 KB
    __shared__ __align__(16) float hA[2][HH][8];      // 3.2 KB each
    __shared__ __align__(16) float hB[2][HH][8];
    __shared__ __align__(16) float hC[2][HH][8];
    __shared__ float sink;

    // 14 batches per block = 6 + 4 + 4 over three independent warp-groups,
    // one block per SM (grid 147). Cap b0 -> tail batches recomputed
    // identically by two blocks (benign duplicate writes).
    const int b0  = min((int)blockIdx.x * 14, 2048 - 14);
    const int tid = threadIdx.x;

    if (tid < 128) {
        run_group<3, 1, 8>(xA, hA, &sink, b0, tid, 0,
                           x, W_ih, W_hh, b_ih, b_hh, fc_w, fc_b, out);
    } else if (tid < 256) {
        run_group<2, 2, 4>(xB, hB, &sink, b0 + 6, tid - 128, 140,
                           x, W_ih, W_hh, b_ih, b_hh, fc_w, fc_b, out);
    } else {
        run_group<2, 3, 4>(xC, hC, &sink, b0 + 10, tid - 256, 280,
                           x, W_ih, W_hh, b_ih, b_hh, fc_w, fc_b, out);
    }
}

extern "C" void kernel_launch(void* const* d_in, const int* in_sizes, int n_in,
                              void* d_out, int out_size) {
    const float* x    = (const float*)d_in[0];
    const float* W_ih = (const float*)d_in[1];
    const float* W_hh = (const float*)d_in[2];
    const float* b_ih = (const float*)d_in[3];
    const float* b_hh = (const float*)d_in[4];
    const float* fc_w = (const float*)d_in[5];
    const float* fc_b = (const float*)d_in[6];
    lstm_fused<<<147, 384>>>(x, W_ih, W_hh, b_ih, b_hh, fc_w, fc_b, (float*)d_out);
}